// round 11
// baseline (speedup 1.0000x reference)
#include <cuda_runtime.h>
#include <cuda_bf16.h>
#include <float.h>

#define NS 512
#define EMB 256

// scratch (device globals — no allocation allowed)
__device__ float  g_G[NS * NS];     // gram matrix E·E^T
__device__ float  g_diag[NS];       // diagonal = squared norms
__device__ double g_loss;
__device__ int    g_count;
__device__ int    g_done;

// Kernel 1: G = E·E^T. 64x64 tiles, 4x4 register micro-tile, smem stored
// K-transposed so operand fetch is LDS.128. FFMA-bound (~1:8 LDS:FFMA).
__global__ void dot_kernel(const float* __restrict__ E) {
    if (blockIdx.x == 0 && blockIdx.y == 0 && threadIdx.x == 0) {
        g_loss = 0.0; g_count = 0; g_done = 0;
    }
    // [k][row] layout; 68 = 64+4 pad, row stride 272B (16B-aligned)
    __shared__ float As[16][68];
    __shared__ float Bs[16][68];
    const int tid = threadIdx.x;           // 0..255
    const int tx = tid & 15;               // 0..15 -> col group
    const int ty = tid >> 4;               // 0..15 -> row group
    const int r0 = blockIdx.y * 64;
    const int c0 = blockIdx.x * 64;
    const int lrow = tid >> 2;             // 0..63
    const int lc4  = (tid & 3) * 4;        // 0,4,8,12

    float acc[4][4] = {};

    for (int k0 = 0; k0 < EMB; k0 += 16) {
        float4 av = *(const float4*)&E[(r0 + lrow) * EMB + k0 + lc4];
        float4 bv = *(const float4*)&E[(c0 + lrow) * EMB + k0 + lc4];
        __syncthreads();                   // previous compute done before overwrite
        As[lc4 + 0][lrow] = av.x; As[lc4 + 1][lrow] = av.y;
        As[lc4 + 2][lrow] = av.z; As[lc4 + 3][lrow] = av.w;
        Bs[lc4 + 0][lrow] = bv.x; Bs[lc4 + 1][lrow] = bv.y;
        Bs[lc4 + 2][lrow] = bv.z; Bs[lc4 + 3][lrow] = bv.w;
        __syncthreads();
#pragma unroll
        for (int k = 0; k < 16; k++) {
            float4 a = *(const float4*)&As[k][ty * 4];
            float4 b = *(const float4*)&Bs[k][tx * 4];
            acc[0][0] += a.x * b.x; acc[0][1] += a.x * b.y;
            acc[0][2] += a.x * b.z; acc[0][3] += a.x * b.w;
            acc[1][0] += a.y * b.x; acc[1][1] += a.y * b.y;
            acc[1][2] += a.y * b.z; acc[1][3] += a.y * b.w;
            acc[2][0] += a.z * b.x; acc[2][1] += a.z * b.y;
            acc[2][2] += a.z * b.z; acc[2][3] += a.z * b.w;
            acc[3][0] += a.w * b.x; acc[3][1] += a.w * b.y;
            acc[3][2] += a.w * b.z; acc[3][3] += a.w * b.w;
        }
    }

#pragma unroll
    for (int a = 0; a < 4; a++) {
        int row = r0 + ty * 4 + a;
        float4 v = make_float4(acc[a][0], acc[a][1], acc[a][2], acc[a][3]);
        *(float4*)&g_G[row * NS + c0 + tx * 4] = v;
#pragma unroll
        for (int b = 0; b < 4; b++) {
            int col = c0 + tx * 4 + b;
            if (row == col) g_diag[row] = acc[a][b];
        }
    }
}

// Kernel 2: per-anchor block, 512 threads (16 warps) -> ~1 positive pair
// per warp, single MLP-4 load batch each; full-row float4 prefetch and
// precomputed smem thresholds keep the hot path register-only.
__global__ void pair_kernel(const float* __restrict__ R,
                            const int* __restrict__ lab,
                            float* __restrict__ out, int out_size) {
    const int i = blockIdx.x;
    const int t = threadIdx.x;
    const int wid = t >> 5, lane = t & 31;

    __shared__ float Drow[NS];
    __shared__ float adj[NS];     // labs[n]==li ? +INF : Drow[n]-MARGIN
    __shared__ int   labs[NS];
    const float di = g_diag[i];
    const int   li = lab[i];
    for (int n = t; n < NS; n += 512) {
        int   ln = lab[n];
        float D  = di + g_diag[n] - 2.0f * g_G[i * NS + n];
        Drow[n] = D;
        labs[n] = ln;
        adj[n]  = (ln == li) ? FLT_MAX : (D - 3.0f);
    }
    __syncthreads();

    const float4* __restrict__ adj4 = (const float4*)adj;
    const float4 a0 = adj4[lane];
    const float4 a1 = adj4[lane + 32];
    const float4 a2 = adj4[lane + 64];
    const float4 a3 = adj4[lane + 96];
    const int nb0 = lane * 4;

    double wloss = 0.0;
    int    wcount = 0;

    for (int j = i + 1 + wid; j < NS; j += 16) {
        if (labs[j] != li) continue;       // warp-uniform
        const float Dij = Drow[j];
        const float4* __restrict__ R4 =
            (const float4*)(R + ((size_t)i * NS + (size_t)j) * (size_t)NS);

        // 4 independent LDG.128 per lane — full row prefetched, MLP=4
        float4 r0 = R4[lane];
        float4 r1 = R4[lane + 32];
        float4 r2 = R4[lane + 64];
        float4 r3 = R4[lane + 96];

        float bs = -1.0f;                  // scores in [0,1); -1 = none
        int   bi = 0x7fffffff;
        // n ascending within lane + strict > ⇒ first-occurrence kept
        if (Dij > a0.x && r0.x > bs) { bs = r0.x; bi = nb0 + 0; }
        if (Dij > a0.y && r0.y > bs) { bs = r0.y; bi = nb0 + 1; }
        if (Dij > a0.z && r0.z > bs) { bs = r0.z; bi = nb0 + 2; }
        if (Dij > a0.w && r0.w > bs) { bs = r0.w; bi = nb0 + 3; }
        if (Dij > a1.x && r1.x > bs) { bs = r1.x; bi = nb0 + 128; }
        if (Dij > a1.y && r1.y > bs) { bs = r1.y; bi = nb0 + 129; }
        if (Dij > a1.z && r1.z > bs) { bs = r1.z; bi = nb0 + 130; }
        if (Dij > a1.w && r1.w > bs) { bs = r1.w; bi = nb0 + 131; }
        if (Dij > a2.x && r2.x > bs) { bs = r2.x; bi = nb0 + 256; }
        if (Dij > a2.y && r2.y > bs) { bs = r2.y; bi = nb0 + 257; }
        if (Dij > a2.z && r2.z > bs) { bs = r2.z; bi = nb0 + 258; }
        if (Dij > a2.w && r2.w > bs) { bs = r2.w; bi = nb0 + 259; }
        if (Dij > a3.x && r3.x > bs) { bs = r3.x; bi = nb0 + 384; }
        if (Dij > a3.y && r3.y > bs) { bs = r3.y; bi = nb0 + 385; }
        if (Dij > a3.z && r3.z > bs) { bs = r3.z; bi = nb0 + 386; }
        if (Dij > a3.w && r3.w > bs) { bs = r3.w; bi = nb0 + 387; }

        // warp argmax, tie-break toward smaller index
        for (int off = 16; off; off >>= 1) {
            float os = __shfl_down_sync(0xffffffffu, bs, off);
            int   oi = __shfl_down_sync(0xffffffffu, bi, off);
            if (os > bs || (os == bs && oi < bi)) { bs = os; bi = oi; }
        }
        if (lane == 0 && bs >= -0.5f) {
            wloss += (double)(Dij - Drow[bi] + 3.0f);
            wcount += 1;
        }
    }
    if (lane == 0 && wcount > 0) {
        atomicAdd(&g_loss, wloss);
        atomicAdd(&g_count, wcount);
    }
    __syncthreads();

    // fused finalize: last block to arrive writes the output
    if (t == 0) {
        __threadfence();
        int prev = atomicAdd(&g_done, 1);
        if (prev == (int)gridDim.x - 1) {
            double l = atomicAdd(&g_loss, 0.0);
            int    c = atomicAdd(&g_count, 0);
            int denom = c > 0 ? c : 1;
            out[0] = (float)(l / (double)denom);
            if (out_size > 1) out[1] = (float)c;
            for (int k = 2; k < out_size; k++) out[k] = 0.0f;
        }
    }
}

extern "C" void kernel_launch(void* const* d_in, const int* in_sizes, int n_in,
                              void* d_out, int out_size) {
    const float* E   = (const float*)d_in[0];   // embeddings [512,256] f32
    const int*   lab = (const int*)d_in[1];     // labels [512] i32
    const float* R   = (const float*)d_in[2];   // rand_u [512,512,512] f32
    float* out = (float*)d_out;

    dim3 gb(NS / 64, NS / 64);
    dot_kernel<<<gb, 256>>>(E);
    pair_kernel<<<NS, 512>>>(R, lab, out, out_size);
}

// round 12
// speedup vs baseline: 1.2323x; 1.2323x over previous
#include <cuda_runtime.h>
#include <cuda_bf16.h>
#include <float.h>

#define NS 512
#define EMB 256

// scratch (device globals — no allocation allowed)
__device__ float  g_G[NS * NS];     // gram matrix E·E^T
__device__ float  g_diag[NS];       // diagonal = squared norms
__device__ double g_loss;
__device__ int    g_count;
__device__ int    g_done;

// Kernel 1: G = E·E^T, 32x32 tiles, 2x2 register blocking (R9 known-good).
__global__ void dot_kernel(const float* __restrict__ E) {
    if (blockIdx.x == 0 && blockIdx.y == 0 && threadIdx.x == 0 && threadIdx.y == 0) {
        g_loss = 0.0; g_count = 0; g_done = 0;
    }
    __shared__ float As[32][34];
    __shared__ float Bs[32][34];
    const int tx = threadIdx.x;            // 0..15
    const int ty = threadIdx.y;            // 0..15
    const int tid = ty * 16 + tx;
    const int r0 = blockIdx.y * 32;
    const int c0 = blockIdx.x * 32;
    const int lrow = tid >> 3;             // 0..31
    const int lcol = (tid & 7) * 4;        // 0,4,...,28

    float acc00 = 0.f, acc01 = 0.f, acc10 = 0.f, acc11 = 0.f;

    for (int k0 = 0; k0 < EMB; k0 += 32) {
        float4 av = *(const float4*)&E[(r0 + lrow) * EMB + k0 + lcol];
        float4 bv = *(const float4*)&E[(c0 + lrow) * EMB + k0 + lcol];
        As[lrow][lcol + 0] = av.x; As[lrow][lcol + 1] = av.y;
        As[lrow][lcol + 2] = av.z; As[lrow][lcol + 3] = av.w;
        Bs[lrow][lcol + 0] = bv.x; Bs[lrow][lcol + 1] = bv.y;
        Bs[lrow][lcol + 2] = bv.z; Bs[lrow][lcol + 3] = bv.w;
        __syncthreads();
#pragma unroll
        for (int k = 0; k < 32; k += 2) {
            float2 a0 = *(const float2*)&As[ty][k];
            float2 a1 = *(const float2*)&As[ty + 16][k];
            float2 b0 = *(const float2*)&Bs[tx][k];
            float2 b1 = *(const float2*)&Bs[tx + 16][k];
            acc00 += a0.x * b0.x + a0.y * b0.y;
            acc01 += a0.x * b1.x + a0.y * b1.y;
            acc10 += a1.x * b0.x + a1.y * b0.y;
            acc11 += a1.x * b1.x + a1.y * b1.y;
        }
        __syncthreads();
    }

    int r_a = r0 + ty, r_b = r0 + ty + 16;
    int c_a = c0 + tx, c_b = c0 + tx + 16;
    g_G[r_a * NS + c_a] = acc00;
    g_G[r_a * NS + c_b] = acc01;
    g_G[r_b * NS + c_a] = acc10;
    g_G[r_b * NS + c_b] = acc11;
    if (r_a == c_a) g_diag[r_a] = acc00;
    if (r_a == c_b) g_diag[r_a] = acc01;
    if (r_b == c_a) g_diag[r_b] = acc10;
    if (r_b == c_b) g_diag[r_b] = acc11;
}

// Kernel 2: per-anchor block (256 thr). Positive pairs compacted into a
// shared list, then each warp walks the list with the NEXT pair's R row
// loads issued before the current pair's compare/reduce (MLP up to 8).
__global__ void pair_kernel(const float* __restrict__ R,
                            const int* __restrict__ lab,
                            float* __restrict__ out, int out_size) {
    const int i = blockIdx.x;
    const int t = threadIdx.x;
    const int wid = t >> 5, lane = t & 31;

    __shared__ float Drow[NS];
    __shared__ float adj[NS];     // labs[n]==li ? +INF : Drow[n]-MARGIN
    __shared__ int   labs[NS];
    __shared__ int   pos[NS];     // compacted positive-j list (order-free)
    __shared__ int   m;
    const float di = g_diag[i];
    const int   li = lab[i];
    if (t == 0) m = 0;
    for (int n = t; n < NS; n += 256) {
        int   ln = lab[n];
        float D  = di + g_diag[n] - 2.0f * g_G[i * NS + n];
        Drow[n] = D;
        labs[n] = ln;
        adj[n]  = (ln == li) ? FLT_MAX : (D - 3.0f);
    }
    __syncthreads();
    for (int n = i + 1 + t; n < NS; n += 256) {
        if (labs[n] == li) pos[atomicAdd(&m, 1)] = n;
    }
    __syncthreads();
    const int mm = m;

    const float4* __restrict__ adj4 = (const float4*)adj;
    const float4 a0 = adj4[lane];
    const float4 a1 = adj4[lane + 32];
    const float4 a2 = adj4[lane + 64];
    const float4 a3 = adj4[lane + 96];
    const int nb0 = lane * 4;
    const size_t ibase = (size_t)i * NS * NS;

    double wloss = 0.0;
    int    wcount = 0;

    int p = wid;
    float4 r0, r1, r2, r3;
    float  Dij = 0.0f;
    if (p < mm) {
        int j = pos[p];                       // warp-uniform
        Dij = Drow[j];
        const float4* R4 = (const float4*)(R + ibase + (size_t)j * NS);
        r0 = R4[lane]; r1 = R4[lane + 32]; r2 = R4[lane + 64]; r3 = R4[lane + 96];
    }
    while (p < mm) {
        const int pn = p + 8;
        float4 s0, s1, s2, s3;
        float  Dn = 0.0f;
        if (pn < mm) {                        // prefetch next pair's row
            int jn = pos[pn];
            Dn = Drow[jn];
            const float4* R4n = (const float4*)(R + ibase + (size_t)jn * NS);
            s0 = R4n[lane]; s1 = R4n[lane + 32];
            s2 = R4n[lane + 64]; s3 = R4n[lane + 96];
        }

        float bs = -1.0f;                     // scores in [0,1); -1 = none
        int   bi = 0x7fffffff;
        // n ascending within lane + strict > ⇒ first-occurrence kept
        if (Dij > a0.x && r0.x > bs) { bs = r0.x; bi = nb0 + 0; }
        if (Dij > a0.y && r0.y > bs) { bs = r0.y; bi = nb0 + 1; }
        if (Dij > a0.z && r0.z > bs) { bs = r0.z; bi = nb0 + 2; }
        if (Dij > a0.w && r0.w > bs) { bs = r0.w; bi = nb0 + 3; }
        if (Dij > a1.x && r1.x > bs) { bs = r1.x; bi = nb0 + 128; }
        if (Dij > a1.y && r1.y > bs) { bs = r1.y; bi = nb0 + 129; }
        if (Dij > a1.z && r1.z > bs) { bs = r1.z; bi = nb0 + 130; }
        if (Dij > a1.w && r1.w > bs) { bs = r1.w; bi = nb0 + 131; }
        if (Dij > a2.x && r2.x > bs) { bs = r2.x; bi = nb0 + 256; }
        if (Dij > a2.y && r2.y > bs) { bs = r2.y; bi = nb0 + 257; }
        if (Dij > a2.z && r2.z > bs) { bs = r2.z; bi = nb0 + 258; }
        if (Dij > a2.w && r2.w > bs) { bs = r2.w; bi = nb0 + 259; }
        if (Dij > a3.x && r3.x > bs) { bs = r3.x; bi = nb0 + 384; }
        if (Dij > a3.y && r3.y > bs) { bs = r3.y; bi = nb0 + 385; }
        if (Dij > a3.z && r3.z > bs) { bs = r3.z; bi = nb0 + 386; }
        if (Dij > a3.w && r3.w > bs) { bs = r3.w; bi = nb0 + 387; }

        // warp argmax, tie-break toward smaller index
        for (int off = 16; off; off >>= 1) {
            float os = __shfl_down_sync(0xffffffffu, bs, off);
            int   oi = __shfl_down_sync(0xffffffffu, bi, off);
            if (os > bs || (os == bs && oi < bi)) { bs = os; bi = oi; }
        }
        if (lane == 0 && bs >= -0.5f) {
            wloss += (double)(Dij - Drow[bi] + 3.0f);
            wcount += 1;
        }

        p = pn; Dij = Dn;
        r0 = s0; r1 = s1; r2 = s2; r3 = s3;
    }
    if (lane == 0 && wcount > 0) {
        atomicAdd(&g_loss, wloss);
        atomicAdd(&g_count, wcount);
    }
    __syncthreads();

    // fused finalize: last block to arrive writes the output
    if (t == 0) {
        __threadfence();
        int prev = atomicAdd(&g_done, 1);
        if (prev == (int)gridDim.x - 1) {
            double l = atomicAdd(&g_loss, 0.0);
            int    c = atomicAdd(&g_count, 0);
            int denom = c > 0 ? c : 1;
            out[0] = (float)(l / (double)denom);
            if (out_size > 1) out[1] = (float)c;
            for (int k = 2; k < out_size; k++) out[k] = 0.0f;
        }
    }
}

extern "C" void kernel_launch(void* const* d_in, const int* in_sizes, int n_in,
                              void* d_out, int out_size) {
    const float* E   = (const float*)d_in[0];   // embeddings [512,256] f32
    const int*   lab = (const int*)d_in[1];     // labels [512] i32
    const float* R   = (const float*)d_in[2];   // rand_u [512,512,512] f32
    float* out = (float*)d_out;

    dim3 gb(NS / 32, NS / 32), tb(16, 16);
    dot_kernel<<<gb, tb>>>(E);
    pair_kernel<<<NS, 256>>>(R, lab, out, out_size);
}